// round 3
// baseline (speedup 1.0000x reference)
#include <cuda_runtime.h>
#include <cuda_bf16.h>
#include <math.h>

#define BB 64
#define CC 512
#define KK 64
#define HW 4096
#define NSPLIT 8
#define GRP 8

#define XSTR 18    // smem tile row stride in bf16
#define LSTR 132   // logits smem stride in floats

// ---- scratch (device globals; no allocation allowed) ----
__device__ __align__(16) __nv_bfloat16 g_wb[KK * CC];
__device__ __align__(16) float         g_rnorm[BB * HW];
__device__ __align__(16) __nv_bfloat16 g_assign[(size_t)BB * KK * HW];
__device__ __align__(16) float         g_asum_part[BB * KK * 32];
__device__ __align__(16) float         g_vpart[(size_t)NSPLIT * BB * KK * CC];
__device__ __align__(16) float         g_gss[BB * KK];

// ---------------- mma.sync bf16 m16n8k16 ----------------
__device__ __forceinline__ void mma16816(float* d, const unsigned* a, const unsigned* b) {
    asm volatile(
        "mma.sync.aligned.m16n8k16.row.col.f32.bf16.bf16.f32 "
        "{%0,%1,%2,%3}, {%4,%5,%6,%7}, {%8,%9}, {%0,%1,%2,%3};"
        : "+f"(d[0]), "+f"(d[1]), "+f"(d[2]), "+f"(d[3])
        : "r"(a[0]), "r"(a[1]), "r"(a[2]), "r"(a[3]), "r"(b[0]), "r"(b[1]));
}

__device__ __forceinline__ unsigned pack_bf2(float lo, float hi) {
    __nv_bfloat162 p = __floats2bfloat162_rn(lo, hi);
    return *reinterpret_cast<unsigned*>(&p);
}

// ---------------- K_pre: convert conv_w to bf16 ----------------
__global__ void k_pre(const float* __restrict__ w) {
    int t = blockIdx.x * 256 + threadIdx.x;
    if (t < KK * CC) g_wb[t] = __float2bfloat16(w[t]);
}

// ---------------- K2: fused norm + logits GEMM + softmax (double-buffered) ----
// grid (HW/128, GRP), 256 threads.
__global__ __launch_bounds__(256) void k_logits(const float* __restrict__ x,
                                                const float* __restrict__ conv_b,
                                                int b0) {
    __shared__ __align__(16) char smA[KK * LSTR * 4];   // overlay: mainloop bufs / Ls
    __shared__ float ssq[256];
    __shared__ float rnorm_s[128];
    __shared__ float bias_s[KK];

    const int b  = b0 + blockIdx.y;
    const int bi = blockIdx.x;
    const int i0 = bi * 128;
    const int t  = threadIdx.x;
    const int lane = t & 31, warp = t >> 5;
    const int mw = warp >> 1, nw = warp & 1;
    const int g = lane >> 2, tg = lane & 3;

    if (t < KK) bias_s[t] = conv_b[t];

    const float* xb = x + (size_t)b * CC * HW + i0;
    const unsigned* wb32 = reinterpret_cast<const unsigned*>(g_wb);
    const int iL = t & 127, chalf = t >> 7;

    float* Ls = reinterpret_cast<float*>(smA);

    float acc[8][4];
#pragma unroll
    for (int nt = 0; nt < 8; nt++)
#pragma unroll
        for (int q = 0; q < 4; q++) acc[nt][q] = 0.f;
    float ssq_loc = 0.f;

    const int wk = t >> 3, wc = t & 7;

    float xr[8];
    unsigned wr[2];
#pragma unroll
    for (int j = 0; j < 8; j++) xr[j] = xb[(size_t)(chalf * 8 + j) * HW + iL];
    wr[0] = wb32[wk * (CC / 2) + wc];
    wr[1] = wb32[(wk + 32) * (CC / 2) + wc];
    {
        __nv_bfloat16* Ws = reinterpret_cast<__nv_bfloat16*>(smA);
        __nv_bfloat16* Xs = reinterpret_cast<__nv_bfloat16*>(smA + 4608);
        *reinterpret_cast<unsigned*>(&Ws[wk * XSTR + wc * 2]) = wr[0];
        *reinterpret_cast<unsigned*>(&Ws[(wk + 32) * XSTR + wc * 2]) = wr[1];
#pragma unroll
        for (int j = 0; j < 4; j++) {
            ssq_loc += xr[2 * j] * xr[2 * j] + xr[2 * j + 1] * xr[2 * j + 1];
            *reinterpret_cast<unsigned*>(&Xs[iL * XSTR + chalf * 8 + 2 * j]) =
                pack_bf2(xr[2 * j], xr[2 * j + 1]);
        }
    }
    __syncthreads();

    for (int it = 0; it < 32; it++) {
        const int c1 = (it + 1) * 16;
        if (it < 31) {
#pragma unroll
            for (int j = 0; j < 8; j++)
                xr[j] = xb[(size_t)(c1 + chalf * 8 + j) * HW + iL];
            wr[0] = wb32[wk * (CC / 2) + (c1 >> 1) + wc];
            wr[1] = wb32[(wk + 32) * (CC / 2) + (c1 >> 1) + wc];
        }

        const int s = it & 1;
        __nv_bfloat16* Ws = reinterpret_cast<__nv_bfloat16*>(smA + s * 2304);
        __nv_bfloat16* Xs = reinterpret_cast<__nv_bfloat16*>(smA + 4608 + s * 4608);

        unsigned a[4];
        a[0] = *reinterpret_cast<unsigned*>(&Ws[(mw * 16 + g) * XSTR + tg * 2]);
        a[1] = *reinterpret_cast<unsigned*>(&Ws[(mw * 16 + g + 8) * XSTR + tg * 2]);
        a[2] = *reinterpret_cast<unsigned*>(&Ws[(mw * 16 + g) * XSTR + tg * 2 + 8]);
        a[3] = *reinterpret_cast<unsigned*>(&Ws[(mw * 16 + g + 8) * XSTR + tg * 2 + 8]);
#pragma unroll
        for (int nt = 0; nt < 8; nt++) {
            int col = nw * 64 + nt * 8 + g;
            unsigned bf[2];
            bf[0] = *reinterpret_cast<unsigned*>(&Xs[col * XSTR + tg * 2]);
            bf[1] = *reinterpret_cast<unsigned*>(&Xs[col * XSTR + tg * 2 + 8]);
            mma16816(acc[nt], a, bf);
        }

        if (it < 31) {
            const int sn = s ^ 1;
            __nv_bfloat16* Wn = reinterpret_cast<__nv_bfloat16*>(smA + sn * 2304);
            __nv_bfloat16* Xn = reinterpret_cast<__nv_bfloat16*>(smA + 4608 + sn * 4608);
            *reinterpret_cast<unsigned*>(&Wn[wk * XSTR + wc * 2]) = wr[0];
            *reinterpret_cast<unsigned*>(&Wn[(wk + 32) * XSTR + wc * 2]) = wr[1];
#pragma unroll
            for (int j = 0; j < 4; j++) {
                ssq_loc += xr[2 * j] * xr[2 * j] + xr[2 * j + 1] * xr[2 * j + 1];
                *reinterpret_cast<unsigned*>(&Xn[iL * XSTR + chalf * 8 + 2 * j]) =
                    pack_bf2(xr[2 * j], xr[2 * j + 1]);
            }
        }
        __syncthreads();
    }

    // reduce sum(x^2) -> rnorm
    ssq[t] = ssq_loc;
    __syncthreads();
    if (t < 128) {
        float s = ssq[t] + ssq[t + 128];
        float rn = 1.f / fmaxf(sqrtf(s), 1e-12f);
        rnorm_s[t] = rn;
        g_rnorm[b * HW + i0 + t] = rn;
    }
    __syncthreads();   // buffers dead; Ls overlay becomes live

    // epilogue: logits -> Ls
#pragma unroll
    for (int nt = 0; nt < 8; nt++) {
        int col = nw * 64 + nt * 8 + tg * 2;
        int row = mw * 16 + g;
        float r0 = rnorm_s[col], r1 = rnorm_s[col + 1];
        Ls[row * LSTR + col]           = acc[nt][0] * r0 + bias_s[row];
        Ls[row * LSTR + col + 1]       = acc[nt][1] * r1 + bias_s[row];
        Ls[(row + 8) * LSTR + col]     = acc[nt][2] * r0 + bias_s[row + 8];
        Ls[(row + 8) * LSTR + col + 1] = acc[nt][3] * r1 + bias_s[row + 8];
    }
    __syncthreads();

    // softmax over k: 2 threads per column, 32 clusters each; write a back to Ls
    {
        const int col = t >> 1, kh = (t & 1) * 32;
        float m = -1e30f;
#pragma unroll 8
        for (int k2 = 0; k2 < 32; k2++) m = fmaxf(m, Ls[(kh + k2) * LSTR + col]);
        m = fmaxf(m, __shfl_xor_sync(0xffffffffu, m, 1));
        float s = 0.f;
#pragma unroll 8
        for (int k2 = 0; k2 < 32; k2++) {
            float e = __expf(Ls[(kh + k2) * LSTR + col] - m);
            Ls[(kh + k2) * LSTR + col] = e;
            s += e;
        }
        s += __shfl_xor_sync(0xffffffffu, s, 1);
        float inv = 1.f / s;
#pragma unroll 8
        for (int k2 = 0; k2 < 32; k2++) {
            float a = Ls[(kh + k2) * LSTR + col] * inv;
            Ls[(kh + k2) * LSTR + col] = a;
            g_assign[((size_t)(b * KK + kh + k2)) * HW + i0 + col] = __float2bfloat16(a);
        }
    }
    __syncthreads();

    // per-tile asum partials (fp32, deterministic)
    if (t < KK) {
        float s = 0.f;
        for (int c = 0; c < 128; c++) s += Ls[t * LSTR + c];
        g_asum_part[(b * KK + t) * 32 + bi] = s;
    }
}

// ---------------- K3: vlad GEMM (split-K over i, double-buffered) ----------------
// grid (4 c2-tiles, NSPLIT, GRP), 256 threads.
__global__ __launch_bounds__(256) void k_vlad(const float* __restrict__ x, int b0) {
    __shared__ __align__(16) char smB[2 * 2304 + 2 * 4608];
    __shared__ float rnorm_s[8 * 128];

    const int c2b = blockIdx.x * 128;
    const int split = blockIdx.y;
    const int b = b0 + blockIdx.z;
    const int t = threadIdx.x;
    const int lane = t & 31, warp = t >> 5;
    const int mw = warp >> 1, nw = warp & 1;
    const int g = lane >> 2, tg = lane & 3;

    for (int u = t; u < 1024; u += 256) {
        int j8 = u >> 7, cl = u & 127;
        rnorm_s[u] = g_rnorm[b * HW + j8 * 512 + c2b + cl];
    }

    const float* xb = x + (size_t)b * CC * HW;
    const unsigned* asg32 =
        reinterpret_cast<const unsigned*>(g_assign + (size_t)b * KK * HW);

    const int iL = t & 127, ihalf = t >> 7;
    const int wk = t >> 3, wc = t & 7;

    float acc[8][4];
#pragma unroll
    for (int nt = 0; nt < 8; nt++)
#pragma unroll
        for (int q = 0; q < 4; q++) acc[nt][q] = 0.f;

    const int ibase0 = split * (HW / NSPLIT);

    float xr[8];
    unsigned wr[2];
#pragma unroll
    for (int j = 0; j < 8; j++)
        xr[j] = xb[(size_t)(ibase0 + ihalf * 8 + j) * 512 + c2b + iL];
    wr[0] = asg32[wk * (HW / 2) + (ibase0 >> 1) + wc];
    wr[1] = asg32[(wk + 32) * (HW / 2) + (ibase0 >> 1) + wc];
    __syncthreads();   // rnorm_s ready
    {
        __nv_bfloat16* As = reinterpret_cast<__nv_bfloat16*>(smB);
        __nv_bfloat16* Xs = reinterpret_cast<__nv_bfloat16*>(smB + 4608);
        *reinterpret_cast<unsigned*>(&As[wk * XSTR + wc * 2]) = wr[0];
        *reinterpret_cast<unsigned*>(&As[(wk + 32) * XSTR + wc * 2]) = wr[1];
#pragma unroll
        for (int j = 0; j < 4; j++) {
            int i2 = ihalf * 8 + 2 * j;
            float v0 = xr[2 * j]     * rnorm_s[(2 * j)     * 128 + iL];
            float v1 = xr[2 * j + 1] * rnorm_s[(2 * j + 1) * 128 + iL];
            // note: (i&7) for i = ihalf*8+j equals j since ihalf*8 is multiple of 8
            *reinterpret_cast<unsigned*>(&Xs[iL * XSTR + i2]) = pack_bf2(v0, v1);
        }
    }
    __syncthreads();

    const int NIT = (HW / NSPLIT) / 16;
    for (int it = 0; it < NIT; it++) {
        const int ibn = ibase0 + (it + 1) * 16;
        if (it < NIT - 1) {
#pragma unroll
            for (int j = 0; j < 8; j++)
                xr[j] = xb[(size_t)(ibn + ihalf * 8 + j) * 512 + c2b + iL];
            wr[0] = asg32[wk * (HW / 2) + (ibn >> 1) + wc];
            wr[1] = asg32[(wk + 32) * (HW / 2) + (ibn >> 1) + wc];
        }

        const int s = it & 1;
        __nv_bfloat16* As = reinterpret_cast<__nv_bfloat16*>(smB + s * 2304);
        __nv_bfloat16* Xs = reinterpret_cast<__nv_bfloat16*>(smB + 4608 + s * 4608);

        unsigned a[4];
        a[0] = *reinterpret_cast<unsigned*>(&As[(mw * 16 + g) * XSTR + tg * 2]);
        a[1] = *reinterpret_cast<unsigned*>(&As[(mw * 16 + g + 8) * XSTR + tg * 2]);
        a[2] = *reinterpret_cast<unsigned*>(&As[(mw * 16 + g) * XSTR + tg * 2 + 8]);
        a[3] = *reinterpret_cast<unsigned*>(&As[(mw * 16 + g + 8) * XSTR + tg * 2 + 8]);
#pragma unroll
        for (int nt = 0; nt < 8; nt++) {
            int col = nw * 64 + nt * 8 + g;
            unsigned bf[2];
            bf[0] = *reinterpret_cast<unsigned*>(&Xs[col * XSTR + tg * 2]);
            bf[1] = *reinterpret_cast<unsigned*>(&Xs[col * XSTR + tg * 2 + 8]);
            mma16816(acc[nt], a, bf);
        }

        if (it < NIT - 1) {
            const int sn = s ^ 1;
            __nv_bfloat16* An = reinterpret_cast<__nv_bfloat16*>(smB + sn * 2304);
            __nv_bfloat16* Xn = reinterpret_cast<__nv_bfloat16*>(smB + 4608 + sn * 4608);
            *reinterpret_cast<unsigned*>(&An[wk * XSTR + wc * 2]) = wr[0];
            *reinterpret_cast<unsigned*>(&An[(wk + 32) * XSTR + wc * 2]) = wr[1];
#pragma unroll
            for (int j = 0; j < 4; j++) {
                int i2 = ihalf * 8 + 2 * j;
                float v0 = xr[2 * j]     * rnorm_s[(2 * j)     * 128 + iL];
                float v1 = xr[2 * j + 1] * rnorm_s[(2 * j + 1) * 128 + iL];
                *reinterpret_cast<unsigned*>(&Xn[iL * XSTR + i2]) = pack_bf2(v0, v1);
            }
        }
        __syncthreads();
    }

    float* vp = g_vpart + ((size_t)(split * BB + b)) * KK * CC;
#pragma unroll
    for (int nt = 0; nt < 8; nt++) {
        int col = c2b + nw * 64 + nt * 8 + tg * 2;
        int row = mw * 16 + g;
        vp[row * CC + col]           = acc[nt][0];
        vp[row * CC + col + 1]       = acc[nt][1];
        vp[(row + 8) * CC + col]     = acc[nt][2];
        vp[(row + 8) * CC + col + 1] = acc[nt][3];
    }
}

// ---------------- K4a: per-(b,k) combine + intra-normalize ----------------
// grid (KK, BB), 128 threads.
__global__ __launch_bounds__(128) void k_intra(const float* __restrict__ cent,
                                               float* __restrict__ out) {
    __shared__ float red[4];
    __shared__ float bcastA, bcastR;

    const int k = blockIdx.x, b = blockIdx.y;
    const int t = threadIdx.x;
    const int lane = t & 31, warp = t >> 5;

    // asum from 32 fp32 partials (warp 0)
    if (warp == 0) {
        float s = g_asum_part[(b * KK + k) * 32 + lane];
#pragma unroll
        for (int o = 16; o > 0; o >>= 1) s += __shfl_down_sync(0xffffffffu, s, o);
        if (lane == 0) bcastA = s;
    }
    __syncthreads();
    const float as = bcastA;

    const size_t base = ((size_t)(b * KK + k)) * CC;
    const float4 cc = reinterpret_cast<const float4*>(cent + k * CC)[t];
    float4 v4 = make_float4(-as * cc.x, -as * cc.y, -as * cc.z, -as * cc.w);
#pragma unroll
    for (int s = 0; s < NSPLIT; s++) {
        const float4 a =
            reinterpret_cast<const float4*>(g_vpart + (size_t)s * BB * KK * CC + base)[t];
        v4.x += a.x; v4.y += a.y; v4.z += a.z; v4.w += a.w;
    }
    float ss = v4.x * v4.x + v4.y * v4.y + v4.z * v4.z + v4.w * v4.w;
#pragma unroll
    for (int o = 16; o > 0; o >>= 1) ss += __shfl_down_sync(0xffffffffu, ss, o);
    if (lane == 0) red[warp] = ss;
    __syncthreads();
    if (t == 0) {
        float tot = red[0] + red[1] + red[2] + red[3];
        float rinv = 1.f / fmaxf(sqrtf(tot), 1e-12f);
        bcastR = rinv;
        g_gss[b * KK + k] = tot * rinv * rinv;
    }
    __syncthreads();
    const float rinv = bcastR;
    float4 y;
    y.x = v4.x * rinv; y.y = v4.y * rinv; y.z = v4.z * rinv; y.w = v4.w * rinv;
    reinterpret_cast<float4*>(out + base)[t] = y;
}

// ---------------- K4b: global L2 normalize ----------------
__global__ __launch_bounds__(256) void k_gnorm(float* __restrict__ out) {
    __shared__ float red[8];
    __shared__ float bcast;
    const int b = blockIdx.x, t = threadIdx.x;
    const int lane = t & 31, warp = t >> 5;

    float s = (t < KK) ? g_gss[b * KK + t] : 0.f;
#pragma unroll
    for (int o = 16; o > 0; o >>= 1) s += __shfl_down_sync(0xffffffffu, s, o);
    if (lane == 0) red[warp] = s;
    __syncthreads();
    if (t == 0) {
        float tot = red[0] + red[1];
        bcast = 1.f / fmaxf(sqrtf(tot), 1e-12f);
    }
    __syncthreads();
    const float gr = bcast;
    float4* ob = reinterpret_cast<float4*>(out + (size_t)b * KK * CC);
#pragma unroll 4
    for (int u = t; u < KK * CC / 4; u += 256) {
        float4 v = ob[u];
        v.x *= gr; v.y *= gr; v.z *= gr; v.w *= gr;
        ob[u] = v;
    }
}

// ---------------- launch ----------------
extern "C" void kernel_launch(void* const* d_in, const int* in_sizes, int n_in,
                              void* d_out, int out_size) {
    (void)in_sizes; (void)n_in; (void)out_size;
    const float* x    = (const float*)d_in[0];
    const float* w    = (const float*)d_in[1];
    const float* bias = (const float*)d_in[2];
    const float* cent = (const float*)d_in[3];
    float* out = (float*)d_out;

    k_pre<<<128, 256>>>(w);
    for (int g = 0; g < BB / GRP; g++) {
        k_logits<<<dim3(HW / 128, GRP), 256>>>(x, bias, g * GRP);
        k_vlad<<<dim3(4, NSPLIT, GRP), 256>>>(x, g * GRP);
    }
    k_intra<<<dim3(KK, BB), 128>>>(cent, out);
    k_gnorm<<<BB, 256>>>(out);
}

// round 4
// speedup vs baseline: 1.5418x; 1.5418x over previous
#include <cuda_runtime.h>
#include <cuda_bf16.h>
#include <math.h>

#define BB 64
#define CC 512
#define KK 64
#define HW 4096
#define NSPLIT 4

// smem tile geometry (u32 units)
#define ASTR 10     // A tile: 64 rows x 8 kpairs, stride 10 u32
#define BSTR 136    // B tile: 8 kpair-rows x 128 cols, stride 136 u32

// ---- scratch (device globals; no allocation allowed) ----
__device__ __align__(16) __nv_bfloat16 g_wb[KK * CC];
__device__ __align__(16) float         g_rnorm[BB * HW];
__device__ __align__(16) __nv_bfloat16 g_assign[(size_t)BB * KK * HW];
__device__ __align__(16) float         g_asum_part[BB * KK * 32];
__device__ __align__(16) float         g_vpart[(size_t)NSPLIT * BB * KK * CC];
__device__ __align__(16) float         g_gss[BB * KK];

__device__ __forceinline__ void mma16816(float* d, const unsigned* a, const unsigned* b) {
    asm volatile(
        "mma.sync.aligned.m16n8k16.row.col.f32.bf16.bf16.f32 "
        "{%0,%1,%2,%3}, {%4,%5,%6,%7}, {%8,%9}, {%0,%1,%2,%3};"
        : "+f"(d[0]), "+f"(d[1]), "+f"(d[2]), "+f"(d[3])
        : "r"(a[0]), "r"(a[1]), "r"(a[2]), "r"(a[3]), "r"(b[0]), "r"(b[1]));
}

__device__ __forceinline__ unsigned pack_bf2(float lo, float hi) {
    __nv_bfloat162 p = __floats2bfloat162_rn(lo, hi);
    return *reinterpret_cast<unsigned*>(&p);
}

// ---------------- K_pre ----------------
__global__ void k_pre(const float* __restrict__ w) {
    int t = blockIdx.x * 256 + threadIdx.x;
    if (t < KK * CC) g_wb[t] = __float2bfloat16(w[t]);
}

// ---------------- K2: norm + logits GEMM + register softmax ----------------
// grid (HW/128, BB), 256 threads
__global__ __launch_bounds__(256) void k_logits(const float* __restrict__ x,
                                                const float* __restrict__ conv_b) {
    __shared__ __align__(16) char smA[13824];
    __shared__ float rnorm_s[128];
    __shared__ float bias_s[KK];

    const int b  = blockIdx.y;
    const int bi = blockIdx.x;
    const int i0 = bi * 128;
    const int t  = threadIdx.x;
    const int lane = t & 31, warp = t >> 5;
    const int mw = warp >> 1, nw = warp & 1;
    const int g = lane >> 2, tg = lane & 3;

    if (t < KK) bias_s[t] = conv_b[t];

    const float* xb = x + (size_t)b * CC * HW + i0;
    const uint2* wb64 = reinterpret_cast<const uint2*>(g_wb);

    const int i4 = t & 31, c2g = t >> 5;   // x loader: 2 channels (2*c2g,2*c2g+1), 4 cols
    const int wrow = t >> 2, wpp = t & 3;  // w loader: row, kpair-pair

    unsigned* W0 = (unsigned*)smA;
    unsigned* W1 = (unsigned*)(smA + 2560);
    unsigned* X0 = (unsigned*)(smA + 5120);
    unsigned* X1 = (unsigned*)(smA + 9472);

    float acc[8][4];
#pragma unroll
    for (int nt = 0; nt < 8; nt++)
#pragma unroll
        for (int q = 0; q < 4; q++) acc[nt][q] = 0.f;
    float4 ssq4 = make_float4(0.f, 0.f, 0.f, 0.f);

    float4 xa0, xa1;
    uint2 wv;
    // prologue: load chunk 0
    xa0 = *reinterpret_cast<const float4*>(xb + (size_t)(2 * c2g) * HW + i4 * 4);
    xa1 = *reinterpret_cast<const float4*>(xb + (size_t)(2 * c2g + 1) * HW + i4 * 4);
    wv  = wb64[wrow * (CC / 4) + wpp];
    {
        ssq4.x += xa0.x * xa0.x + xa1.x * xa1.x;
        ssq4.y += xa0.y * xa0.y + xa1.y * xa1.y;
        ssq4.z += xa0.z * xa0.z + xa1.z * xa1.z;
        ssq4.w += xa0.w * xa0.w + xa1.w * xa1.w;
        uint4 p = make_uint4(pack_bf2(xa0.x, xa1.x), pack_bf2(xa0.y, xa1.y),
                             pack_bf2(xa0.z, xa1.z), pack_bf2(xa0.w, xa1.w));
        *reinterpret_cast<uint4*>(X0 + c2g * BSTR + i4 * 4) = p;
        *reinterpret_cast<uint2*>(W0 + wrow * ASTR + wpp * 2) = wv;
    }
    __syncthreads();

    for (int it = 0; it < 32; it++) {
        const int c1 = (it + 1) * 16;
        if (it < 31) {
            xa0 = *reinterpret_cast<const float4*>(xb + (size_t)(c1 + 2 * c2g) * HW + i4 * 4);
            xa1 = *reinterpret_cast<const float4*>(xb + (size_t)(c1 + 2 * c2g + 1) * HW + i4 * 4);
            wv  = wb64[wrow * (CC / 4) + (c1 >> 2) + wpp];
        }
        const int s = it & 1;
        unsigned* Ws = s ? W1 : W0;
        unsigned* Xs = s ? X1 : X0;

        unsigned a[4];
        const int row = mw * 16 + g;
        a[0] = Ws[row * ASTR + tg];
        a[1] = Ws[(row + 8) * ASTR + tg];
        a[2] = Ws[row * ASTR + tg + 4];
        a[3] = Ws[(row + 8) * ASTR + tg + 4];
#pragma unroll
        for (int nt = 0; nt < 8; nt++) {
            const int col = nw * 64 + nt * 8 + g;
            unsigned bf[2];
            bf[0] = Xs[tg * BSTR + col];
            bf[1] = Xs[(tg + 4) * BSTR + col];
            mma16816(acc[nt], a, bf);
        }

        if (it < 31) {
            unsigned* Wn = s ? W0 : W1;
            unsigned* Xn = s ? X0 : X1;
            ssq4.x += xa0.x * xa0.x + xa1.x * xa1.x;
            ssq4.y += xa0.y * xa0.y + xa1.y * xa1.y;
            ssq4.z += xa0.z * xa0.z + xa1.z * xa1.z;
            ssq4.w += xa0.w * xa0.w + xa1.w * xa1.w;
            uint4 p = make_uint4(pack_bf2(xa0.x, xa1.x), pack_bf2(xa0.y, xa1.y),
                                 pack_bf2(xa0.z, xa1.z), pack_bf2(xa0.w, xa1.w));
            *reinterpret_cast<uint4*>(Xn + c2g * BSTR + i4 * 4) = p;
            *reinterpret_cast<uint2*>(Wn + wrow * ASTR + wpp * 2) = wv;
        }
        __syncthreads();
    }

    // ---- ssq -> rnorm ----
    float4* ssq_sm = reinterpret_cast<float4*>(smA);        // [8][32]
    ssq_sm[c2g * 32 + i4] = ssq4;
    __syncthreads();
    if (t < 32) {
        float4 s = ssq_sm[t];
#pragma unroll
        for (int r = 1; r < 8; r++) {
            float4 u = ssq_sm[r * 32 + t];
            s.x += u.x; s.y += u.y; s.z += u.z; s.w += u.w;
        }
        float4 rn;
        rn.x = 1.f / fmaxf(sqrtf(s.x), 1e-12f);
        rn.y = 1.f / fmaxf(sqrtf(s.y), 1e-12f);
        rn.z = 1.f / fmaxf(sqrtf(s.z), 1e-12f);
        rn.w = 1.f / fmaxf(sqrtf(s.w), 1e-12f);
        reinterpret_cast<float4*>(rnorm_s)[t] = rn;
        *reinterpret_cast<float4*>(g_rnorm + (size_t)b * HW + i0 + t * 4) = rn;
    }
    __syncthreads();

    float* colmax4 = reinterpret_cast<float*>(smA + 4096);  // [128][4]
    float* colsum4 = reinterpret_cast<float*>(smA + 6144);  // [128][4]
    float* asum2   = reinterpret_cast<float*>(smA + 8192);  // [64][2]

    const int row = mw * 16 + g;
    const float b0v = bias_s[row], b1v = bias_s[row + 8];

    // logits in place
#pragma unroll
    for (int nt = 0; nt < 8; nt++) {
        const int col = nw * 64 + nt * 8 + tg * 2;
        const float r0 = rnorm_s[col], r1 = rnorm_s[col + 1];
        acc[nt][0] = acc[nt][0] * r0 + b0v;
        acc[nt][1] = acc[nt][1] * r1 + b0v;
        acc[nt][2] = acc[nt][2] * r0 + b1v;
        acc[nt][3] = acc[nt][3] * r1 + b1v;
    }

    // per-col max across this warp's rows
    float mA[8], mB[8];
#pragma unroll
    for (int nt = 0; nt < 8; nt++) {
        mA[nt] = fmaxf(acc[nt][0], acc[nt][2]);
        mB[nt] = fmaxf(acc[nt][1], acc[nt][3]);
    }
#pragma unroll
    for (int off = 4; off < 32; off <<= 1) {
#pragma unroll
        for (int nt = 0; nt < 8; nt++) {
            mA[nt] = fmaxf(mA[nt], __shfl_xor_sync(0xffffffffu, mA[nt], off));
            mB[nt] = fmaxf(mB[nt], __shfl_xor_sync(0xffffffffu, mB[nt], off));
        }
    }
    if (g == 0) {
#pragma unroll
        for (int nt = 0; nt < 8; nt++) {
            const int col = nw * 64 + nt * 8 + tg * 2;
            colmax4[col * 4 + mw] = mA[nt];
            colmax4[(col + 1) * 4 + mw] = mB[nt];
        }
    }
    __syncthreads();

    // exp + per-col sum
    float sA[8], sB[8];
#pragma unroll
    for (int nt = 0; nt < 8; nt++) {
        const int col = nw * 64 + nt * 8 + tg * 2;
        float4 c0 = *reinterpret_cast<float4*>(colmax4 + col * 4);
        float4 c1 = *reinterpret_cast<float4*>(colmax4 + (col + 1) * 4);
        float m0 = fmaxf(fmaxf(c0.x, c0.y), fmaxf(c0.z, c0.w));
        float m1 = fmaxf(fmaxf(c1.x, c1.y), fmaxf(c1.z, c1.w));
        acc[nt][0] = __expf(acc[nt][0] - m0);
        acc[nt][2] = __expf(acc[nt][2] - m0);
        acc[nt][1] = __expf(acc[nt][1] - m1);
        acc[nt][3] = __expf(acc[nt][3] - m1);
        sA[nt] = acc[nt][0] + acc[nt][2];
        sB[nt] = acc[nt][1] + acc[nt][3];
    }
#pragma unroll
    for (int off = 4; off < 32; off <<= 1) {
#pragma unroll
        for (int nt = 0; nt < 8; nt++) {
            sA[nt] += __shfl_xor_sync(0xffffffffu, sA[nt], off);
            sB[nt] += __shfl_xor_sync(0xffffffffu, sB[nt], off);
        }
    }
    if (g == 0) {
#pragma unroll
        for (int nt = 0; nt < 8; nt++) {
            const int col = nw * 64 + nt * 8 + tg * 2;
            colsum4[col * 4 + mw] = sA[nt];
            colsum4[(col + 1) * 4 + mw] = sB[nt];
        }
    }
    __syncthreads();

    // normalize, store assign bf16, accumulate row sums
    unsigned* asg = reinterpret_cast<unsigned*>(g_assign) + (size_t)(b * KK) * (HW / 2);
    float rowsum = 0.f, rowsum8 = 0.f;
#pragma unroll
    for (int nt = 0; nt < 8; nt++) {
        const int col = nw * 64 + nt * 8 + tg * 2;
        float4 s0 = *reinterpret_cast<float4*>(colsum4 + col * 4);
        float4 s1 = *reinterpret_cast<float4*>(colsum4 + (col + 1) * 4);
        float inv0 = 1.f / (s0.x + s0.y + s0.z + s0.w);
        float inv1 = 1.f / (s1.x + s1.y + s1.z + s1.w);
        float a00 = acc[nt][0] * inv0, a01 = acc[nt][1] * inv1;
        float a02 = acc[nt][2] * inv0, a03 = acc[nt][3] * inv1;
        asg[(size_t)row * (HW / 2) + (i0 + col) / 2]       = pack_bf2(a00, a01);
        asg[(size_t)(row + 8) * (HW / 2) + (i0 + col) / 2] = pack_bf2(a02, a03);
        rowsum  += a00 + a01;
        rowsum8 += a02 + a03;
    }
#pragma unroll
    for (int off = 1; off < 4; off <<= 1) {
        rowsum  += __shfl_xor_sync(0xffffffffu, rowsum, off);
        rowsum8 += __shfl_xor_sync(0xffffffffu, rowsum8, off);
    }
    if (tg == 0) {
        asum2[row * 2 + nw] = rowsum;
        asum2[(row + 8) * 2 + nw] = rowsum8;
    }
    __syncthreads();
    if (t < KK)
        g_asum_part[(b * KK + t) * 32 + bi] = asum2[t * 2] + asum2[t * 2 + 1];
}

// ---------------- K3: vlad GEMM (split-K over i) ----------------
// grid (4, NSPLIT, BB), 256 threads
__global__ __launch_bounds__(256) void k_vlad(const float* __restrict__ x) {
    __shared__ __align__(16) char smB[13824];
    __shared__ __align__(16) float4 rn4[8 * 32];

    const int c2b = blockIdx.x * 128;
    const int split = blockIdx.y;
    const int b = blockIdx.z;
    const int t = threadIdx.x;
    const int lane = t & 31, warp = t >> 5;
    const int mw = warp >> 1, nw = warp & 1;
    const int g = lane >> 2, tg = lane & 3;

    // rnorm tile: index [(i&7)*32 + c4] as float4 over cols c2b+c4*4..+3
    {
        const int j8 = t >> 5, c4l = t & 31;
        rn4[t] = *reinterpret_cast<const float4*>(
            g_rnorm + (size_t)b * HW + j8 * 512 + c2b + c4l * 4);
    }

    const float* xb = x + (size_t)b * CC * HW;
    const uint2* asg64 = reinterpret_cast<const uint2*>(g_assign + (size_t)b * KK * HW);

    const int i2 = t >> 5, c4 = t & 31;    // x loader: i-pair (2*i2,2*i2+1), 4 cols
    const int arow = t >> 2, app = t & 3;  // assign loader

    unsigned* A0 = (unsigned*)smB;
    unsigned* A1 = (unsigned*)(smB + 2560);
    unsigned* X0 = (unsigned*)(smB + 5120);
    unsigned* X1 = (unsigned*)(smB + 9472);

    float acc[8][4];
#pragma unroll
    for (int nt = 0; nt < 8; nt++)
#pragma unroll
        for (int q = 0; q < 4; q++) acc[nt][q] = 0.f;

    const int ibase0 = split * (HW / NSPLIT);

    float4 xa0, xa1;
    uint2 av;
    xa0 = *reinterpret_cast<const float4*>(xb + (size_t)(ibase0 + 2 * i2) * 512 + c2b + c4 * 4);
    xa1 = *reinterpret_cast<const float4*>(xb + (size_t)(ibase0 + 2 * i2 + 1) * 512 + c2b + c4 * 4);
    av  = asg64[arow * (HW / 4) + (ibase0 >> 2) + app];
    __syncthreads();   // rn4 ready
    {
        float4 r0 = rn4[(2 * (i2 & 3)) * 32 + c4];
        float4 r1 = rn4[(2 * (i2 & 3) + 1) * 32 + c4];
        uint4 p = make_uint4(pack_bf2(xa0.x * r0.x, xa1.x * r1.x),
                             pack_bf2(xa0.y * r0.y, xa1.y * r1.y),
                             pack_bf2(xa0.z * r0.z, xa1.z * r1.z),
                             pack_bf2(xa0.w * r0.w, xa1.w * r1.w));
        *reinterpret_cast<uint4*>(X0 + i2 * BSTR + c4 * 4) = p;
        *reinterpret_cast<uint2*>(A0 + arow * ASTR + app * 2) = av;
    }
    __syncthreads();

    const int NIT = (HW / NSPLIT) / 16;
    for (int it = 0; it < NIT; it++) {
        const int ibn = ibase0 + (it + 1) * 16;
        if (it < NIT - 1) {
            xa0 = *reinterpret_cast<const float4*>(xb + (size_t)(ibn + 2 * i2) * 512 + c2b + c4 * 4);
            xa1 = *reinterpret_cast<const float4*>(xb + (size_t)(ibn + 2 * i2 + 1) * 512 + c2b + c4 * 4);
            av  = asg64[arow * (HW / 4) + (ibn >> 2) + app];
        }
        const int s = it & 1;
        unsigned* As = s ? A1 : A0;
        unsigned* Xs = s ? X1 : X0;

        unsigned a[4];
        const int row = mw * 16 + g;
        a[0] = As[row * ASTR + tg];
        a[1] = As[(row + 8) * ASTR + tg];
        a[2] = As[row * ASTR + tg + 4];
        a[3] = As[(row + 8) * ASTR + tg + 4];
#pragma unroll
        for (int nt = 0; nt < 8; nt++) {
            const int col = nw * 64 + nt * 8 + g;
            unsigned bf[2];
            bf[0] = Xs[tg * BSTR + col];
            bf[1] = Xs[(tg + 4) * BSTR + col];
            mma16816(acc[nt], a, bf);
        }

        if (it < NIT - 1) {
            unsigned* An = s ? A0 : A1;
            unsigned* Xn = s ? X0 : X1;
            float4 r0 = rn4[(2 * (i2 & 3)) * 32 + c4];
            float4 r1 = rn4[(2 * (i2 & 3) + 1) * 32 + c4];
            uint4 p = make_uint4(pack_bf2(xa0.x * r0.x, xa1.x * r1.x),
                                 pack_bf2(xa0.y * r0.y, xa1.y * r1.y),
                                 pack_bf2(xa0.z * r0.z, xa1.z * r1.z),
                                 pack_bf2(xa0.w * r0.w, xa1.w * r1.w));
            *reinterpret_cast<uint4*>(Xn + i2 * BSTR + c4 * 4) = p;
            *reinterpret_cast<uint2*>(An + arow * ASTR + app * 2) = av;
        }
        __syncthreads();
    }

    float* vp = g_vpart + ((size_t)(split * BB + b)) * KK * CC;
#pragma unroll
    for (int nt = 0; nt < 8; nt++) {
        const int col = c2b + nw * 64 + nt * 8 + tg * 2;
        const int row = mw * 16 + g;
        *reinterpret_cast<float2*>(vp + (size_t)row * CC + col) =
            make_float2(acc[nt][0], acc[nt][1]);
        *reinterpret_cast<float2*>(vp + (size_t)(row + 8) * CC + col) =
            make_float2(acc[nt][2], acc[nt][3]);
    }
}

// ---------------- K4a: combine + intra-normalize ----------------
__global__ __launch_bounds__(128) void k_intra(const float* __restrict__ cent,
                                               float* __restrict__ out) {
    __shared__ float red[4];
    __shared__ float bcastA, bcastR;

    const int k = blockIdx.x, b = blockIdx.y;
    const int t = threadIdx.x;
    const int lane = t & 31, warp = t >> 5;

    if (warp == 0) {
        float s = g_asum_part[(b * KK + k) * 32 + lane];
#pragma unroll
        for (int o = 16; o > 0; o >>= 1) s += __shfl_down_sync(0xffffffffu, s, o);
        if (lane == 0) bcastA = s;
    }
    __syncthreads();
    const float as = bcastA;

    const size_t base = ((size_t)(b * KK + k)) * CC;
    const float4 cc = reinterpret_cast<const float4*>(cent + k * CC)[t];
    float4 v4 = make_float4(-as * cc.x, -as * cc.y, -as * cc.z, -as * cc.w);
#pragma unroll
    for (int s = 0; s < NSPLIT; s++) {
        const float4 a =
            reinterpret_cast<const float4*>(g_vpart + (size_t)s * BB * KK * CC + base)[t];
        v4.x += a.x; v4.y += a.y; v4.z += a.z; v4.w += a.w;
    }
    float ss = v4.x * v4.x + v4.y * v4.y + v4.z * v4.z + v4.w * v4.w;
#pragma unroll
    for (int o = 16; o > 0; o >>= 1) ss += __shfl_down_sync(0xffffffffu, ss, o);
    if (lane == 0) red[warp] = ss;
    __syncthreads();
    if (t == 0) {
        float tot = red[0] + red[1] + red[2] + red[3];
        float rinv = 1.f / fmaxf(sqrtf(tot), 1e-12f);
        bcastR = rinv;
        g_gss[b * KK + k] = tot * rinv * rinv;
    }
    __syncthreads();
    const float rinv = bcastR;
    float4 y;
    y.x = v4.x * rinv; y.y = v4.y * rinv; y.z = v4.z * rinv; y.w = v4.w * rinv;
    reinterpret_cast<float4*>(out + base)[t] = y;
}

// ---------------- K4b: global L2 normalize ----------------
__global__ __launch_bounds__(256) void k_gnorm(float* __restrict__ out) {
    __shared__ float red[8];
    __shared__ float bcast;
    const int b = blockIdx.x, t = threadIdx.x;
    const int lane = t & 31, warp = t >> 5;

    float s = (t < KK) ? g_gss[b * KK + t] : 0.f;
#pragma unroll
    for (int o = 16; o > 0; o >>= 1) s += __shfl_down_sync(0xffffffffu, s, o);
    if (lane == 0) red[warp] = s;
    __syncthreads();
    if (t == 0) {
        float tot = red[0] + red[1];
        bcast = 1.f / fmaxf(sqrtf(tot), 1e-12f);
    }
    __syncthreads();
    const float gr = bcast;
    float4* ob = reinterpret_cast<float4*>(out + (size_t)b * KK * CC);
#pragma unroll 4
    for (int u = t; u < KK * CC / 4; u += 256) {
        float4 v = ob[u];
        v.x *= gr; v.y *= gr; v.z *= gr; v.w *= gr;
        ob[u] = v;
    }
}

// ---------------- launch ----------------
extern "C" void kernel_launch(void* const* d_in, const int* in_sizes, int n_in,
                              void* d_out, int out_size) {
    (void)in_sizes; (void)n_in; (void)out_size;
    const float* x    = (const float*)d_in[0];
    const float* w    = (const float*)d_in[1];
    const float* bias = (const float*)d_in[2];
    const float* cent = (const float*)d_in[3];
    float* out = (float*)d_out;

    k_pre<<<128, 256>>>(w);
    k_logits<<<dim3(HW / 128, BB), 256>>>(x, bias);
    k_vlad<<<dim3(4, NSPLIT, BB), 256>>>(x);
    k_intra<<<dim3(KK, BB), 128>>>(cent, out);
    k_gnorm<<<BB, 256>>>(out);
}

// round 5
// speedup vs baseline: 2.0009x; 1.2978x over previous
#include <cuda_runtime.h>
#include <cuda_bf16.h>
#include <math.h>

#define BB 64
#define CC 512
#define KK 64
#define HW 4096
#define NSPLIT 4

#define AST 20     // A tile row stride (u32): 64 rows x 16 kpairs
#define BST 136    // B tile row stride (u32): 16 kpair-rows x 128 cols

// ---- scratch (device globals; no allocation allowed) ----
__device__ __align__(16) __nv_bfloat16 g_wb[KK * CC];
__device__ __align__(16) float         g_rnorm[BB * HW];
__device__ __align__(16) __nv_bfloat16 g_assign[(size_t)BB * KK * HW];
__device__ __align__(16) float         g_asum_part[BB * KK * 32];
__device__ __align__(16) float         g_vpart[(size_t)NSPLIT * BB * KK * CC];
__device__ __align__(16) float         g_gss[BB * KK];

__device__ __forceinline__ void mma16816(float* d, const unsigned* a, const unsigned* b) {
    asm volatile(
        "mma.sync.aligned.m16n8k16.row.col.f32.bf16.bf16.f32 "
        "{%0,%1,%2,%3}, {%4,%5,%6,%7}, {%8,%9}, {%0,%1,%2,%3};"
        : "+f"(d[0]), "+f"(d[1]), "+f"(d[2]), "+f"(d[3])
        : "r"(a[0]), "r"(a[1]), "r"(a[2]), "r"(a[3]), "r"(b[0]), "r"(b[1]));
}

__device__ __forceinline__ unsigned pack_bf2(float lo, float hi) {
    __nv_bfloat162 p = __floats2bfloat162_rn(lo, hi);
    return *reinterpret_cast<unsigned*>(&p);
}

__device__ __forceinline__ void cpasync16(unsigned* smem, const void* gmem) {
    unsigned s = (unsigned)__cvta_generic_to_shared(smem);
    asm volatile("cp.async.ca.shared.global [%0], [%1], 16;\n" :: "r"(s), "l"(gmem));
}
__device__ __forceinline__ void cp_commit() {
    asm volatile("cp.async.commit_group;\n");
}
__device__ __forceinline__ void cp_wait0() {
    asm volatile("cp.async.wait_group 0;\n");
}

// ---------------- K_pre ----------------
__global__ void k_pre(const float* __restrict__ w) {
    int t = blockIdx.x * 256 + threadIdx.x;
    if (t < KK * CC) g_wb[t] = __float2bfloat16(w[t]);
}

// ---------------- K2: norm + logits GEMM + register softmax ----------------
// grid (HW/128, BB), 256 threads, K-chunk = 32 channels
__global__ __launch_bounds__(256) void k_logits(const float* __restrict__ x,
                                                const float* __restrict__ conv_b) {
    __shared__ __align__(16) unsigned smW[2 * KK * AST];    // 10240 B
    __shared__ __align__(16) unsigned smX[2 * 16 * BST];    // 17408 B
    __shared__ float rnorm_s[128];
    __shared__ float bias_s[KK];

    const int b  = blockIdx.y;
    const int bi = blockIdx.x;
    const int i0 = bi * 128;
    const int t  = threadIdx.x;
    const int lane = t & 31, warp = t >> 5;
    const int mw = warp >> 1, nw = warp & 1;
    const int g = lane >> 2, tg = lane & 3;

    if (t < KK) bias_s[t] = conv_b[t];

    const float* xb = x + (size_t)b * CC * HW + i0;
    const unsigned* wb32 = reinterpret_cast<const unsigned*>(g_wb);

    const int c4 = t & 31, cg = t >> 5;    // X loader: 4 cols, 4 channels
    const int wrow = t >> 2, wq = t & 3;   // W loader (cp.async 16B)

    float acc[8][4];
#pragma unroll
    for (int nt = 0; nt < 8; nt++)
#pragma unroll
        for (int q = 0; q < 4; q++) acc[nt][q] = 0.f;
    float4 ssq4 = make_float4(0.f, 0.f, 0.f, 0.f);

    float4 xr[4];
    // ---- prologue: chunk 0 ----
    cpasync16(smW + wrow * AST + wq * 4, wb32 + wrow * (CC / 2) + wq * 4);
    cp_commit();
#pragma unroll
    for (int r = 0; r < 4; r++)
        xr[r] = *reinterpret_cast<const float4*>(xb + (size_t)(4 * cg + r) * HW + c4 * 4);
    {
        ssq4.x += xr[0].x * xr[0].x + xr[1].x * xr[1].x + xr[2].x * xr[2].x + xr[3].x * xr[3].x;
        ssq4.y += xr[0].y * xr[0].y + xr[1].y * xr[1].y + xr[2].y * xr[2].y + xr[3].y * xr[3].y;
        ssq4.z += xr[0].z * xr[0].z + xr[1].z * xr[1].z + xr[2].z * xr[2].z + xr[3].z * xr[3].z;
        ssq4.w += xr[0].w * xr[0].w + xr[1].w * xr[1].w + xr[2].w * xr[2].w + xr[3].w * xr[3].w;
        uint4 p0 = make_uint4(pack_bf2(xr[0].x, xr[1].x), pack_bf2(xr[0].y, xr[1].y),
                              pack_bf2(xr[0].z, xr[1].z), pack_bf2(xr[0].w, xr[1].w));
        uint4 p1 = make_uint4(pack_bf2(xr[2].x, xr[3].x), pack_bf2(xr[2].y, xr[3].y),
                              pack_bf2(xr[2].z, xr[3].z), pack_bf2(xr[2].w, xr[3].w));
        *reinterpret_cast<uint4*>(smX + (2 * cg) * BST + c4 * 4) = p0;
        *reinterpret_cast<uint4*>(smX + (2 * cg + 1) * BST + c4 * 4) = p1;
    }
    cp_wait0();
    __syncthreads();

    const int NIT = CC / 32;
    for (int it = 0; it < NIT; it++) {
        const int c1 = (it + 1) * 32;
        const int s = it & 1, sn = s ^ 1;
        if (it < NIT - 1) {
            cpasync16(smW + sn * (KK * AST) + wrow * AST + wq * 4,
                      wb32 + wrow * (CC / 2) + (c1 >> 1) + wq * 4);
            cp_commit();
#pragma unroll
            for (int r = 0; r < 4; r++)
                xr[r] = *reinterpret_cast<const float4*>(
                    xb + (size_t)(c1 + 4 * cg + r) * HW + c4 * 4);
        }

        const unsigned* Ws = smW + s * (KK * AST);
        const unsigned* Xs = smX + s * (16 * BST);
        const int row = mw * 16 + g;
#pragma unroll
        for (int ks = 0; ks < 2; ks++) {
            unsigned a[4];
            a[0] = Ws[row * AST + ks * 8 + tg];
            a[1] = Ws[(row + 8) * AST + ks * 8 + tg];
            a[2] = Ws[row * AST + ks * 8 + tg + 4];
            a[3] = Ws[(row + 8) * AST + ks * 8 + tg + 4];
#pragma unroll
            for (int nt = 0; nt < 8; nt++) {
                const int col = nw * 64 + nt * 8 + g;
                unsigned bf[2];
                bf[0] = Xs[(ks * 8 + tg) * BST + col];
                bf[1] = Xs[(ks * 8 + tg + 4) * BST + col];
                mma16816(acc[nt], a, bf);
            }
        }

        if (it < NIT - 1) {
            unsigned* Xn = smX + sn * (16 * BST);
            ssq4.x += xr[0].x * xr[0].x + xr[1].x * xr[1].x + xr[2].x * xr[2].x + xr[3].x * xr[3].x;
            ssq4.y += xr[0].y * xr[0].y + xr[1].y * xr[1].y + xr[2].y * xr[2].y + xr[3].y * xr[3].y;
            ssq4.z += xr[0].z * xr[0].z + xr[1].z * xr[1].z + xr[2].z * xr[2].z + xr[3].z * xr[3].z;
            ssq4.w += xr[0].w * xr[0].w + xr[1].w * xr[1].w + xr[2].w * xr[2].w + xr[3].w * xr[3].w;
            uint4 p0 = make_uint4(pack_bf2(xr[0].x, xr[1].x), pack_bf2(xr[0].y, xr[1].y),
                                  pack_bf2(xr[0].z, xr[1].z), pack_bf2(xr[0].w, xr[1].w));
            uint4 p1 = make_uint4(pack_bf2(xr[2].x, xr[3].x), pack_bf2(xr[2].y, xr[3].y),
                                  pack_bf2(xr[2].z, xr[3].z), pack_bf2(xr[2].w, xr[3].w));
            *reinterpret_cast<uint4*>(Xn + (2 * cg) * BST + c4 * 4) = p0;
            *reinterpret_cast<uint4*>(Xn + (2 * cg + 1) * BST + c4 * 4) = p1;
        }
        cp_wait0();
        __syncthreads();
    }

    // ---- ssq -> rnorm ----
    float4* ssq_sm = reinterpret_cast<float4*>(smW);        // [8][32] float4
    ssq_sm[cg * 32 + c4] = ssq4;
    __syncthreads();
    if (t < 32) {
        float4 s = ssq_sm[t];
#pragma unroll
        for (int r = 1; r < 8; r++) {
            float4 u = ssq_sm[r * 32 + t];
            s.x += u.x; s.y += u.y; s.z += u.z; s.w += u.w;
        }
        float4 rn;
        rn.x = 1.f / fmaxf(sqrtf(s.x), 1e-12f);
        rn.y = 1.f / fmaxf(sqrtf(s.y), 1e-12f);
        rn.z = 1.f / fmaxf(sqrtf(s.z), 1e-12f);
        rn.w = 1.f / fmaxf(sqrtf(s.w), 1e-12f);
        reinterpret_cast<float4*>(rnorm_s)[t] = rn;
        *reinterpret_cast<float4*>(g_rnorm + (size_t)b * HW + i0 + t * 4) = rn;
    }
    __syncthreads();

    float* colmax4 = reinterpret_cast<float*>(smX);          // [128][4]
    float* colsum4 = reinterpret_cast<float*>(smX) + 512;    // [128][4]
    float* asum2   = reinterpret_cast<float*>(smX) + 1024;   // [64][2]

    const int row = mw * 16 + g;
    const float b0v = bias_s[row], b1v = bias_s[row + 8];

#pragma unroll
    for (int nt = 0; nt < 8; nt++) {
        const int col = nw * 64 + nt * 8 + tg * 2;
        const float r0 = rnorm_s[col], r1 = rnorm_s[col + 1];
        acc[nt][0] = acc[nt][0] * r0 + b0v;
        acc[nt][1] = acc[nt][1] * r1 + b0v;
        acc[nt][2] = acc[nt][2] * r0 + b1v;
        acc[nt][3] = acc[nt][3] * r1 + b1v;
    }

    float mA[8], mB[8];
#pragma unroll
    for (int nt = 0; nt < 8; nt++) {
        mA[nt] = fmaxf(acc[nt][0], acc[nt][2]);
        mB[nt] = fmaxf(acc[nt][1], acc[nt][3]);
    }
#pragma unroll
    for (int off = 4; off < 32; off <<= 1) {
#pragma unroll
        for (int nt = 0; nt < 8; nt++) {
            mA[nt] = fmaxf(mA[nt], __shfl_xor_sync(0xffffffffu, mA[nt], off));
            mB[nt] = fmaxf(mB[nt], __shfl_xor_sync(0xffffffffu, mB[nt], off));
        }
    }
    if (g == 0) {
#pragma unroll
        for (int nt = 0; nt < 8; nt++) {
            const int col = nw * 64 + nt * 8 + tg * 2;
            colmax4[col * 4 + mw] = mA[nt];
            colmax4[(col + 1) * 4 + mw] = mB[nt];
        }
    }
    __syncthreads();

    float sA[8], sB[8];
#pragma unroll
    for (int nt = 0; nt < 8; nt++) {
        const int col = nw * 64 + nt * 8 + tg * 2;
        float4 c0 = *reinterpret_cast<float4*>(colmax4 + col * 4);
        float4 c1 = *reinterpret_cast<float4*>(colmax4 + (col + 1) * 4);
        float m0 = fmaxf(fmaxf(c0.x, c0.y), fmaxf(c0.z, c0.w));
        float m1 = fmaxf(fmaxf(c1.x, c1.y), fmaxf(c1.z, c1.w));
        acc[nt][0] = __expf(acc[nt][0] - m0);
        acc[nt][2] = __expf(acc[nt][2] - m0);
        acc[nt][1] = __expf(acc[nt][1] - m1);
        acc[nt][3] = __expf(acc[nt][3] - m1);
        sA[nt] = acc[nt][0] + acc[nt][2];
        sB[nt] = acc[nt][1] + acc[nt][3];
    }
#pragma unroll
    for (int off = 4; off < 32; off <<= 1) {
#pragma unroll
        for (int nt = 0; nt < 8; nt++) {
            sA[nt] += __shfl_xor_sync(0xffffffffu, sA[nt], off);
            sB[nt] += __shfl_xor_sync(0xffffffffu, sB[nt], off);
        }
    }
    if (g == 0) {
#pragma unroll
        for (int nt = 0; nt < 8; nt++) {
            const int col = nw * 64 + nt * 8 + tg * 2;
            colsum4[col * 4 + mw] = sA[nt];
            colsum4[(col + 1) * 4 + mw] = sB[nt];
        }
    }
    __syncthreads();

    unsigned* asg = reinterpret_cast<unsigned*>(g_assign) + (size_t)(b * KK) * (HW / 2);
    float rowsum = 0.f, rowsum8 = 0.f;
#pragma unroll
    for (int nt = 0; nt < 8; nt++) {
        const int col = nw * 64 + nt * 8 + tg * 2;
        float4 s0 = *reinterpret_cast<float4*>(colsum4 + col * 4);
        float4 s1 = *reinterpret_cast<float4*>(colsum4 + (col + 1) * 4);
        float inv0 = 1.f / (s0.x + s0.y + s0.z + s0.w);
        float inv1 = 1.f / (s1.x + s1.y + s1.z + s1.w);
        float a00 = acc[nt][0] * inv0, a01 = acc[nt][1] * inv1;
        float a02 = acc[nt][2] * inv0, a03 = acc[nt][3] * inv1;
        asg[(size_t)row * (HW / 2) + (i0 + col) / 2]       = pack_bf2(a00, a01);
        asg[(size_t)(row + 8) * (HW / 2) + (i0 + col) / 2] = pack_bf2(a02, a03);
        rowsum  += a00 + a01;
        rowsum8 += a02 + a03;
    }
#pragma unroll
    for (int off = 1; off < 4; off <<= 1) {
        rowsum  += __shfl_xor_sync(0xffffffffu, rowsum, off);
        rowsum8 += __shfl_xor_sync(0xffffffffu, rowsum8, off);
    }
    if (tg == 0) {
        asum2[row * 2 + nw] = rowsum;
        asum2[(row + 8) * 2 + nw] = rowsum8;
    }
    __syncthreads();
    if (t < KK)
        g_asum_part[(b * KK + t) * 32 + bi] = asum2[t * 2] + asum2[t * 2 + 1];
}

// ---------------- K3: vlad GEMM (split-K over i, i-chunk 32) ----------------
// grid (4, NSPLIT, BB), 256 threads
__global__ __launch_bounds__(256) void k_vlad(const float* __restrict__ x) {
    __shared__ __align__(16) unsigned smA[2 * KK * AST];
    __shared__ __align__(16) unsigned smX[2 * 16 * BST];
    __shared__ __align__(16) float4 rn4[8 * 32];

    const int c2b = blockIdx.x * 128;
    const int split = blockIdx.y;
    const int b = blockIdx.z;
    const int t = threadIdx.x;
    const int lane = t & 31, warp = t >> 5;
    const int mw = warp >> 1, nw = warp & 1;
    const int g = lane >> 2, tg = lane & 3;

    {
        const int j8 = t >> 5, c4l = t & 31;
        rn4[t] = *reinterpret_cast<const float4*>(
            g_rnorm + (size_t)b * HW + j8 * 512 + c2b + c4l * 4);
    }

    const float* xb = x + (size_t)b * CC * HW;
    const unsigned* asg32 = reinterpret_cast<const unsigned*>(g_assign + (size_t)b * KK * HW);

    const int c4 = t & 31, ig = t >> 5;    // X loader: 4 cols, 4 i's
    const int arow = t >> 2, aq = t & 3;   // assign loader (cp.async 16B)

    float acc[8][4];
#pragma unroll
    for (int nt = 0; nt < 8; nt++)
#pragma unroll
        for (int q = 0; q < 4; q++) acc[nt][q] = 0.f;

    const int ibase0 = split * (HW / NSPLIT);

    float4 xr[4];
    cpasync16(smA + arow * AST + aq * 4, asg32 + arow * (HW / 2) + (ibase0 >> 1) + aq * 4);
    cp_commit();
#pragma unroll
    for (int r = 0; r < 4; r++)
        xr[r] = *reinterpret_cast<const float4*>(
            xb + (size_t)(ibase0 + 4 * ig + r) * 512 + c2b + c4 * 4);
    __syncthreads();   // rn4 ready
    {
        uint4 p0, p1;
        {
            float4 rA = rn4[((4 * ig + 0) & 7) * 32 + c4];
            float4 rB = rn4[((4 * ig + 1) & 7) * 32 + c4];
            p0 = make_uint4(pack_bf2(xr[0].x * rA.x, xr[1].x * rB.x),
                            pack_bf2(xr[0].y * rA.y, xr[1].y * rB.y),
                            pack_bf2(xr[0].z * rA.z, xr[1].z * rB.z),
                            pack_bf2(xr[0].w * rA.w, xr[1].w * rB.w));
        }
        {
            float4 rA = rn4[((4 * ig + 2) & 7) * 32 + c4];
            float4 rB = rn4[((4 * ig + 3) & 7) * 32 + c4];
            p1 = make_uint4(pack_bf2(xr[2].x * rA.x, xr[3].x * rB.x),
                            pack_bf2(xr[2].y * rA.y, xr[3].y * rB.y),
                            pack_bf2(xr[2].z * rA.z, xr[3].z * rB.z),
                            pack_bf2(xr[2].w * rA.w, xr[3].w * rB.w));
        }
        *reinterpret_cast<uint4*>(smX + (2 * ig) * BST + c4 * 4) = p0;
        *reinterpret_cast<uint4*>(smX + (2 * ig + 1) * BST + c4 * 4) = p1;
    }
    cp_wait0();
    __syncthreads();

    const int NIT = (HW / NSPLIT) / 32;
    for (int it = 0; it < NIT; it++) {
        const int ibn = ibase0 + (it + 1) * 32;
        const int s = it & 1, sn = s ^ 1;
        if (it < NIT - 1) {
            cpasync16(smA + sn * (KK * AST) + arow * AST + aq * 4,
                      asg32 + arow * (HW / 2) + (ibn >> 1) + aq * 4);
            cp_commit();
#pragma unroll
            for (int r = 0; r < 4; r++)
                xr[r] = *reinterpret_cast<const float4*>(
                    xb + (size_t)(ibn + 4 * ig + r) * 512 + c2b + c4 * 4);
        }

        const unsigned* As = smA + s * (KK * AST);
        const unsigned* Xs = smX + s * (16 * BST);
        const int row = mw * 16 + g;
#pragma unroll
        for (int ks = 0; ks < 2; ks++) {
            unsigned a[4];
            a[0] = As[row * AST + ks * 8 + tg];
            a[1] = As[(row + 8) * AST + ks * 8 + tg];
            a[2] = As[row * AST + ks * 8 + tg + 4];
            a[3] = As[(row + 8) * AST + ks * 8 + tg + 4];
#pragma unroll
            for (int nt = 0; nt < 8; nt++) {
                const int col = nw * 64 + nt * 8 + g;
                unsigned bf[2];
                bf[0] = Xs[(ks * 8 + tg) * BST + col];
                bf[1] = Xs[(ks * 8 + tg + 4) * BST + col];
                mma16816(acc[nt], a, bf);
            }
        }

        if (it < NIT - 1) {
            unsigned* Xn = smX + sn * (16 * BST);
            uint4 p0, p1;
            {
                float4 rA = rn4[((4 * ig + 0) & 7) * 32 + c4];
                float4 rB = rn4[((4 * ig + 1) & 7) * 32 + c4];
                p0 = make_uint4(pack_bf2(xr[0].x * rA.x, xr[1].x * rB.x),
                                pack_bf2(xr[0].y * rA.y, xr[1].y * rB.y),
                                pack_bf2(xr[0].z * rA.z, xr[1].z * rB.z),
                                pack_bf2(xr[0].w * rA.w, xr[1].w * rB.w));
            }
            {
                float4 rA = rn4[((4 * ig + 2) & 7) * 32 + c4];
                float4 rB = rn4[((4 * ig + 3) & 7) * 32 + c4];
                p1 = make_uint4(pack_bf2(xr[2].x * rA.x, xr[3].x * rB.x),
                                pack_bf2(xr[2].y * rA.y, xr[3].y * rB.y),
                                pack_bf2(xr[2].z * rA.z, xr[3].z * rB.z),
                                pack_bf2(xr[2].w * rA.w, xr[3].w * rB.w));
            }
            *reinterpret_cast<uint4*>(Xn + (2 * ig) * BST + c4 * 4) = p0;
            *reinterpret_cast<uint4*>(Xn + (2 * ig + 1) * BST + c4 * 4) = p1;
        }
        cp_wait0();
        __syncthreads();
    }

    float* vp = g_vpart + ((size_t)(split * BB + b)) * KK * CC;
#pragma unroll
    for (int nt = 0; nt < 8; nt++) {
        const int col = c2b + nw * 64 + nt * 8 + tg * 2;
        const int row = mw * 16 + g;
        *reinterpret_cast<float2*>(vp + (size_t)row * CC + col) =
            make_float2(acc[nt][0], acc[nt][1]);
        *reinterpret_cast<float2*>(vp + (size_t)(row + 8) * CC + col) =
            make_float2(acc[nt][2], acc[nt][3]);
    }
}

// ---------------- K4a: combine + intra-normalize ----------------
__global__ __launch_bounds__(128) void k_intra(const float* __restrict__ cent,
                                               float* __restrict__ out) {
    __shared__ float red[4];
    __shared__ float bcastA, bcastR;

    const int k = blockIdx.x, b = blockIdx.y;
    const int t = threadIdx.x;
    const int lane = t & 31, warp = t >> 5;

    if (warp == 0) {
        float s = g_asum_part[(b * KK + k) * 32 + lane];
#pragma unroll
        for (int o = 16; o > 0; o >>= 1) s += __shfl_down_sync(0xffffffffu, s, o);
        if (lane == 0) bcastA = s;
    }
    __syncthreads();
    const float as = bcastA;

    const size_t base = ((size_t)(b * KK + k)) * CC;
    const float4 cc = reinterpret_cast<const float4*>(cent + k * CC)[t];
    float4 v4 = make_float4(-as * cc.x, -as * cc.y, -as * cc.z, -as * cc.w);
#pragma unroll
    for (int s = 0; s < NSPLIT; s++) {
        const float4 a =
            reinterpret_cast<const float4*>(g_vpart + (size_t)s * BB * KK * CC + base)[t];
        v4.x += a.x; v4.y += a.y; v4.z += a.z; v4.w += a.w;
    }
    float ss = v4.x * v4.x + v4.y * v4.y + v4.z * v4.z + v4.w * v4.w;
#pragma unroll
    for (int o = 16; o > 0; o >>= 1) ss += __shfl_down_sync(0xffffffffu, ss, o);
    if (lane == 0) red[warp] = ss;
    __syncthreads();
    if (t == 0) {
        float tot = red[0] + red[1] + red[2] + red[3];
        float rinv = 1.f / fmaxf(sqrtf(tot), 1e-12f);
        bcastR = rinv;
        g_gss[b * KK + k] = tot * rinv * rinv;
    }
    __syncthreads();
    const float rinv = bcastR;
    float4 y;
    y.x = v4.x * rinv; y.y = v4.y * rinv; y.z = v4.z * rinv; y.w = v4.w * rinv;
    reinterpret_cast<float4*>(out + base)[t] = y;
}

// ---------------- K4b: global L2 normalize ----------------
__global__ __launch_bounds__(256) void k_gnorm(float* __restrict__ out) {
    __shared__ float red[8];
    __shared__ float bcast;
    const int b = blockIdx.x, t = threadIdx.x;
    const int lane = t & 31, warp = t >> 5;

    float s = (t < KK) ? g_gss[b * KK + t] : 0.f;
#pragma unroll
    for (int o = 16; o > 0; o >>= 1) s += __shfl_down_sync(0xffffffffu, s, o);
    if (lane == 0) red[warp] = s;
    __syncthreads();
    if (t == 0) {
        float tot = red[0] + red[1];
        bcast = 1.f / fmaxf(sqrtf(tot), 1e-12f);
    }
    __syncthreads();
    const float gr = bcast;
    float4* ob = reinterpret_cast<float4*>(out + (size_t)b * KK * CC);
#pragma unroll 4
    for (int u = t; u < KK * CC / 4; u += 256) {
        float4 v = ob[u];
        v.x *= gr; v.y *= gr; v.z *= gr; v.w *= gr;
        ob[u] = v;
    }
}

// ---------------- launch ----------------
extern "C" void kernel_launch(void* const* d_in, const int* in_sizes, int n_in,
                              void* d_out, int out_size) {
    (void)in_sizes; (void)n_in; (void)out_size;
    const float* x    = (const float*)d_in[0];
    const float* w    = (const float*)d_in[1];
    const float* bias = (const float*)d_in[2];
    const float* cent = (const float*)d_in[3];
    float* out = (float*)d_out;

    k_pre<<<128, 256>>>(w);
    k_logits<<<dim3(HW / 128, BB), 256>>>(x, bias);
    k_vlad<<<dim3(4, NSPLIT, BB), 256>>>(x);
    k_intra<<<dim3(KK, BB), 128>>>(cent, out);
    k_gnorm<<<BB, 256>>>(out);
}